// round 8
// baseline (speedup 1.0000x reference)
#include <cuda_runtime.h>
#include <math_constants.h>

#define NB 96
#define ND 128
#define NPAIR (NB * NB)
#define NCLS 8
#define NUND 4560                 // NB*(NB-1)/2 undirected pairs
#define BTHR 1024
#define MAXBLK 160
#define POSC 1536                 // smem pos-list capacity (expected npos ~560 incl pad)
#define GPOSC 4608                // global fallback capacity (worst case)

// ---------------- device scratch (no allocations allowed) ----------------
__device__ float g_Dm[NPAIR];                   // static-zero diag; off-diag written each run
__device__ __align__(16) float g_fb_d[GPOSC];   // fallback pos list (identical-value writes)
__device__ int   g_fb_m[GPOSC];
__device__ float g_bP[MAXBLK], g_bN[MAXBLK];    // per-block pos/neg distance partials
__device__ int   g_ctrA = 0, g_ctrB = 0;
__device__ volatile int g_flagA = 0;
__device__ float g_pQ[MAXBLK], g_pT[MAXBLK];
__device__ unsigned g_pQC[MAXBLK], g_pTC[MAXBLK];

__device__ __forceinline__ void blk_reduce4(float& a, float& b, unsigned& c1, unsigned& c2,
                                            float* sF1, float* sF2, unsigned* sC1, unsigned* sC2,
                                            int t) {
#pragma unroll
    for (int o = 16; o; o >>= 1) {
        a  += __shfl_down_sync(0xffffffffu, a, o);
        b  += __shfl_down_sync(0xffffffffu, b, o);
        c1 += __shfl_down_sync(0xffffffffu, c1, o);
        c2 += __shfl_down_sync(0xffffffffu, c2, o);
    }
    if ((t & 31) == 0) { sF1[t >> 5] = a; sF2[t >> 5] = b; sC1[t >> 5] = c1; sC2[t >> 5] = c2; }
    __syncthreads();
    if (t < 32) {
        a = sF1[t]; b = sF2[t]; c1 = sC1[t]; c2 = sC2[t];
#pragma unroll
        for (int o = 16; o; o >>= 1) {
            a  += __shfl_down_sync(0xffffffffu, a, o);
            b  += __shfl_down_sync(0xffffffffu, b, o);
            c1 += __shfl_down_sync(0xffffffffu, c1, o);
            c2 += __shfl_down_sync(0xffffffffu, c2, o);
        }
    }
}

__global__ void __launch_bounds__(BTHR, 1)
kFused(const float* __restrict__ E, const void* __restrict__ labp,
       float* __restrict__ out) {
    __shared__ __align__(16) float sPD[POSC];
    __shared__ int   sPM[POSC];
    __shared__ unsigned short sCP[NCLS * BTHR];   // 16 KB
    __shared__ int   sLab[NB];
    __shared__ int   sHist[NCLS];
    __shared__ int   sIs64;
    __shared__ int   sTot[NCLS];
    __shared__ int   sOff[NCLS + 1];
    __shared__ float sWP[32], sWN[32];
    __shared__ float sF1[32], sF2[32];
    __shared__ unsigned sC1[32], sC2[32];
    __shared__ float sThr;
    __shared__ int   sLastFlag;

    const int t = threadIdx.x;
    const int wid = t >> 5, lid = t & 31;
    const int nblk = gridDim.x;

    // ---- labels: int64 (all high words 0, values < 8) or int32 (JAX demotion) ----
    if (t < NCLS) sHist[t] = 0;
    if (t == 0) sIs64 = 1;
    __syncthreads();
    if (t < NB / 2 && ((const int*)labp)[2 * t + 1] != 0) sIs64 = 0;   // benign race
    __syncthreads();
    if (t < NB) {
        int l = sIs64 ? (int)((const long long*)labp)[t] : ((const int*)labp)[t];
        sLab[t] = l;
        atomicAdd(&sHist[l & 7], 1);
    }
    __syncthreads();

    // ================= Phase 1: distance matrix + masked sum partials =================
    float posS = 0.f, negS = 0.f;
    for (int p = blockIdx.x * 32 + wid; p < NUND; p += nblk * 32) {
        // decode undirected pair p -> (i, j), i < j ; offset(i) = i*(191-i)/2
        float s = sqrtf((float)(36481 - 8 * p));
        int i = (int)((191.0f - s) * 0.5f);
        while ((i + 1) * (191 - (i + 1)) / 2 <= p) ++i;
        while (i * (191 - i) / 2 > p) --i;
        int j = i + 1 + (p - i * (191 - i) / 2);
        const float4 a = ((const float4*)(E + i * ND))[lid];
        const float4 b = ((const float4*)(E + j * ND))[lid];
        float dx = a.x - b.x, dy = a.y - b.y, dz = a.z - b.z, dw = a.w - b.w;
        float d2 = dx * dx + dy * dy + dz * dz + dw * dw;
#pragma unroll
        for (int o = 16; o; o >>= 1) d2 += __shfl_down_sync(0xffffffffu, d2, o);
        if (lid == 0) {
            float dm = sqrtf(fmaxf(d2, 0.f) + 1e-16f);
            g_Dm[i * NB + j] = dm;
            g_Dm[j * NB + i] = dm;
            if (sLab[i] == sLab[j]) posS += dm; else negS += dm;
        }
    }
    if (lid == 0) { sWP[wid] = posS; sWN[wid] = negS; }
    __syncthreads();

    // ================= barrier A (grid residency-clamped => spin safe) =================
    if (t == 0) {
        float p = 0.f, n = 0.f;
#pragma unroll
        for (int w = 0; w < 32; w++) { p += sWP[w]; n += sWN[w]; }
        g_bP[blockIdx.x] = p; g_bN[blockIdx.x] = n;
        __threadfence();
        if (atomicAdd(&g_ctrA, 1) == nblk - 1) g_flagA = 1;
        else while (g_flagA == 0) __nanosleep(64);
        __threadfence();
    }
    __syncthreads();

    // ================= Phase 2: per-block redundant build (lean) =================
    // thr (warp 0; deterministic fixed order => identical in every block)
    if (wid == 0) {
        float p = 0.f, n = 0.f;
        for (int w = lid; w < nblk; w += 32) { p += g_bP[w]; n += g_bN[w]; }
#pragma unroll
        for (int o = 16; o; o >>= 1) {
            p += __shfl_down_sync(0xffffffffu, p, o);
            n += __shfl_down_sync(0xffffffffu, n, o);
        }
        if (lid == 0) {
            int s2 = 0;
#pragma unroll
            for (int c = 0; c < NCLS; c++) { int h = sHist[c]; s2 += h * h; }
            float cpos = (float)(s2 - NB);          // directed same-label pair count
            float cneg = (float)(NPAIR - s2);       // directed diff-label pair count
            float mu = (cpos > 0.f && cneg > 0.f)
                       ? ((2.f * n) / cneg - (2.f * p) / cpos) : 0.f;
            sThr = fmaxf(mu, 0.f);
        }
    }

    // pos-list -INF pre-init (pads self-neutralize) + counting pass, all 1024 threads
    {
        for (int x = t; x < POSC; x += BTHR) { sPD[x] = -CUDART_INF_F; sPM[x] = 0; }
        int c8[NCLS];
#pragma unroll
        for (int c = 0; c < NCLS; c++) c8[c] = 0;
        // strided traversal of NPAIR with incremental (ii,jj): 1024 = 10*96 + 64
        int ii = t / NB, jj = t - (t / NB) * NB;
#pragma unroll 1
        for (int it = 0; it < NPAIR / BTHR; it++) {
            if (ii < jj && sLab[ii] == sLab[jj]) {
                int li = sLab[ii];
#pragma unroll
                for (int c = 0; c < NCLS; c++) c8[c] += (li == c);
            }
            jj += 64; ii += 10; if (jj >= NB) { jj -= NB; ii++; }
        }
#pragma unroll
        for (int c = 0; c < NCLS; c++) sCP[c * BTHR + t] = (unsigned short)c8[c];
    }
    __syncthreads();

    // per-class exclusive scan over 1024 counters (warp c handles class c)
    if (wid < NCLS) {
        unsigned short* arr = sCP + wid * BTHR;
        const int b0 = lid * 32;
        int mySum = 0;
#pragma unroll 1
        for (int k = 0; k < 32; k++) mySum += arr[b0 + k];
        int inc = mySum;
#pragma unroll
        for (int o = 1; o < 32; o <<= 1) {
            int x = __shfl_up_sync(0xffffffffu, inc, o);
            if (lid >= o) inc += x;
        }
        int run = inc - mySum;
#pragma unroll 1
        for (int k = 0; k < 32; k++) {
            int v = arr[b0 + k];
            arr[b0 + k] = (unsigned short)run;
            run += v;
        }
        if (lid == 31) sTot[wid] = inc;
    }
    __syncthreads();

    // every thread computes segment bases redundantly in registers
    int sB[NCLS], base8;
    {
        int b = 0;
#pragma unroll
        for (int c = 0; c < NCLS; c++) {
            sB[c] = b;
            b = (b + sTot[c] + 3) & ~3;             // 4-elem aligned segments
        }
        base8 = b;
    }
    if (t < NCLS) sOff[t] = sB[t];
    if (t == NCLS) sOff[NCLS] = ((sOff[NCLS - 1] + sTot[NCLS - 1] + 3) & ~3);
    const bool useS = (base8 <= POSC);
    float* pdW = useS ? sPD : g_fb_d;
    int*   pmW = useS ? sPM : g_fb_m;
    if (!useS) {                                    // rare fallback: init global pads
        for (int x = t; x < base8; x += BTHR) { g_fb_d[x] = -CUDART_INF_F; g_fb_m[x] = 0; }
        __syncthreads();                            // uniform branch: legal
    }

    // scatter pass (same traversal order as counting pass)
    {
        int off[NCLS];
#pragma unroll
        for (int c = 0; c < NCLS; c++) off[c] = sB[c] + (int)sCP[c * BTHR + t];
        int ii = t / NB, jj = t - (t / NB) * NB, idx = t;
#pragma unroll 1
        for (int it = 0; it < NPAIR / BTHR; it++) {
            if (ii < jj && sLab[ii] == sLab[jj]) {
                int li = sLab[ii];
                int s2 = 0;
#pragma unroll
                for (int c = 0; c < NCLS; c++) { if (li == c) s2 = off[c]++; }
                pdW[s2] = g_Dm[idx];
                pmW[s2] = ii | (jj << 8) | (li << 16);
            }
            jj += 64; ii += 10; idx += BTHR; if (jj >= NB) { jj -= NB; ii++; }
        }
    }
    __syncthreads();

    const float thr = sThr, thrh = 0.5f * thr;
    const float* pd = useS ? (const float*)sPD : (const float*)g_fb_d;
    const int*   pm = useS ? (const int*)sPM   : (const int*)g_fb_m;

    // ================= Phase 3: quad + triplet =================
    float qs0 = 0.f, qs1 = 0.f, qs2 = 0.f, qs3 = 0.f, ts = 0.f;
    unsigned qc0 = 0, qc1 = 0, qc2 = 0, qc3 = 0, tc = 0;
    const int gt = blockIdx.x * BTHR + t;
    const int GT = nblk * BTHR;

    // quad: item = (directed pair idx, pos class segment seg, half) — neg pairs only
    const int qTot = NPAIR * NCLS * 2;
    for (int e = gt; e < qTot; e += GT) {
        int idx = e >> 4, seg = (e >> 1) & 7, half = e & 1;
        int ii = idx / NB, jj = idx - ii * NB;
        int cb = sLab[ii];
        if (sLab[jj] == cb) continue;               // not a negative pair (covers ii==jj)
        if (seg == cb) continue;                    // label_j != label_k coupling
        float b = g_Dm[idx];
        const int lo = sOff[seg], hi = sOff[seg + 1];
        const int h = (((hi - lo) >> 1) + 3) & ~3;
        const int xs = half ? lo + h : lo;
        const int xe = half ? hi : lo + h;
        for (int x = xs; x < xe; x += 4) {
            float v0 = pd[x + 0], v1 = pd[x + 1], v2 = pd[x + 2], v3 = pd[x + 3];
            float d0 = b - v0, d1 = b - v1, d2 = b - v2, d3 = b - v3;
            if (d0 < thrh) { qc0++; qs0 += fmaxf(d0, 0.f); }
            if (d1 < thrh) { qc1++; qs1 += fmaxf(d1, 0.f); }
            if (d2 < thrh) { qc2++; qs2 += fmaxf(d2, 0.f); }
            if (d3 < thrh) { qc3++; qs3 += fmaxf(d3, 0.f); }
        }
    }
    float qs = (qs0 + qs1) + (qs2 + qs3);
    unsigned qc = (qc0 + qc1) + (qc2 + qc3);

    // triplet: item = (padded pos slot pp, negative k); both anchor orientations
    for (int e = gt; e < base8 * NB; e += GT) {
        int pp = e / NB, k = e - pp * NB;
        int meta = pm[pp];
        int ai = meta & 255, aj = (meta >> 8) & 255, c = meta >> 16;
        float dij = pd[pp];                         // -INF pads => +INF diffs => skipped
        if (sLab[k] != c) {
            float tv1 = g_Dm[ai * NB + k] - dij;
            float tv2 = g_Dm[aj * NB + k] - dij;
            if (tv1 < thr) { tc++; ts += fmaxf(tv1, 0.f); }
            if (tv2 < thr) { tc++; ts += fmaxf(tv2, 0.f); }
        }
    }

    // ================= Phase 4: reduce + combine =================
    blk_reduce4(qs, ts, qc, tc, sF1, sF2, sC1, sC2, t);
    __syncthreads();
    if (t == 0) {
        g_pQ[blockIdx.x] = qs; g_pT[blockIdx.x] = ts;
        g_pQC[blockIdx.x] = qc; g_pTC[blockIdx.x] = tc;
        __threadfence();
        sLastFlag = (atomicAdd(&g_ctrB, 1) == nblk - 1);
    }
    __syncthreads();
    if (!sLastFlag) return;

    if (t < 32) {
        float a = 0.f, b = 0.f; unsigned c1 = 0, c2 = 0;
        for (int w = t; w < nblk; w += 32) {
            a += g_pQ[w]; b += g_pT[w]; c1 += g_pQC[w]; c2 += g_pTC[w];
        }
#pragma unroll
        for (int o = 16; o; o >>= 1) {
            a  += __shfl_down_sync(0xffffffffu, a, o);
            b  += __shfl_down_sync(0xffffffffu, b, o);
            c1 += __shfl_down_sync(0xffffffffu, c1, o);
            c2 += __shfl_down_sync(0xffffffffu, c2, o);
        }
        if (t == 0) {
            float tl = (c2 > 0) ? b / (float)c2 : 0.f;
            float ql = (c1 > 0) ? a / (float)c1 : 0.f;
            out[0] = tl + ql;
            g_ctrA = 0; g_ctrB = 0; g_flagA = 0;    // reset for next replay
        }
    }
}

extern "C" void kernel_launch(void* const* d_in, const int* in_sizes, int n_in,
                              void* d_out, int out_size) {
    const float* E = (const float*)d_in[0];
    const void* lab = d_in[1];
    (void)in_sizes; (void)n_in; (void)out_size;
    int sms = 148;
    cudaDeviceGetAttribute(&sms, cudaDevAttrMultiProcessorCount, 0);
    // clamp grid to PROVABLE single-wave residency (spin barrier safety)
    int perSM = 1;
    cudaOccupancyMaxActiveBlocksPerMultiprocessor(&perSM, kFused, BTHR, 0);
    if (perSM < 1) perSM = 1;
    long cap = (long)perSM * sms;
    int grid = sms < MAXBLK ? sms : MAXBLK;
    if (grid > cap) grid = (int)cap;
    if (grid < 1) grid = 1;
    kFused<<<grid, BTHR>>>(E, lab, (float*)d_out);
}

// round 9
// speedup vs baseline: 1.3903x; 1.3903x over previous
#include <cuda_runtime.h>
#include <math_constants.h>

#define NB 96
#define ND 128
#define NPAIR (NB * NB)
#define NCLS 8
#define NUND 4560                 // NB*(NB-1)/2 undirected pairs
#define BTHR 1024
#define MAXBLK 160
#define POSC 4608                 // >= worst-case undirected pos (4560) + class padding

// ---------------- device scratch (no allocations allowed) ----------------
__device__ float g_Dm[NPAIR];
__device__ float g_bP[MAXBLK], g_bN[MAXBLK];    // per-block pos/neg distance partials
__device__ int   g_ctrA = 0, g_ctrB = 0;
__device__ volatile int g_flagA = 0;
__device__ float g_pQ[MAXBLK], g_pT[MAXBLK];
__device__ unsigned g_pQC[MAXBLK], g_pTC[MAXBLK];

__global__ void __launch_bounds__(BTHR, 1)
kFused(const float* __restrict__ E, const void* __restrict__ labp,
       float* __restrict__ out) {
    __shared__ __align__(16) float sPD[POSC];   // 18 KB
    __shared__ int   sPM[POSC];                 // 18 KB
    __shared__ int   sLab[NB];
    __shared__ int   sHist[NCLS];
    __shared__ int   sIs64;
    __shared__ unsigned sWT[32 * 4], sWB[32 * 4], sTot4[4];
    __shared__ int   sOff[NCLS + 1];
    __shared__ float sF1[32], sF2[32];
    __shared__ unsigned sC1[32], sC2[32];
    __shared__ float sThr;
    __shared__ int   sLast;

    const int t = threadIdx.x;
    const int wid = t >> 5, lid = t & 31;
    const int nblk = gridDim.x;

    // ---- labels: int64 (values<8 => high words 0) or int32 (JAX demotion) ----
    if (t < NCLS) sHist[t] = 0;
    if (t == 0) sIs64 = 1;
    __syncthreads();
    if (t < NB / 2 && ((const int*)labp)[2 * t + 1] != 0) sIs64 = 0;   // benign race
    __syncthreads();
    if (t < NB) {
        int l = sIs64 ? (int)((const long long*)labp)[t] : ((const int*)labp)[t];
        sLab[t] = l;
        atomicAdd(&sHist[l & 7], 1);
    }
    __syncthreads();

    // ================= Phase 1a: decode my pair + ISSUE E loads =================
    const int p = blockIdx.x * 32 + wid;
    const bool have = p < NUND;
    int pi = 0, pj = 1;
    float4 va = make_float4(0.f, 0.f, 0.f, 0.f), vb = va;
    if (have) {
        float s = sqrtf((float)(36481 - 8 * p));
        int i = (int)((191.0f - s) * 0.5f);
        while ((i + 1) * (191 - (i + 1)) / 2 <= p) ++i;
        while (i * (191 - i) / 2 > p) --i;
        pi = i; pj = i + 1 + (p - i * (191 - i) / 2);
        va = ((const float4*)(E + pi * ND))[lid];     // DRAM loads in flight
        vb = ((const float4*)(E + pj * ND))[lid];     // during counting below
    }

    // ================= counting sort structure (labels only; overlaps loads) ======
    unsigned pk[4] = {0u, 0u, 0u, 0u};    // 8 class counts as 16-bit fields
    {
        int ii = t / NB, jj = t - (t / NB) * NB;
#pragma unroll 1
        for (int it = 0; it < NPAIR / BTHR; it++) {
            if (ii < jj) {
                int li = sLab[ii];
                if (li == sLab[jj]) {
                    unsigned add = 1u << ((li & 1) * 16);
                    int r = li >> 1;
                    pk[0] += (r == 0) ? add : 0u;
                    pk[1] += (r == 1) ? add : 0u;
                    pk[2] += (r == 2) ? add : 0u;
                    pk[3] += (r == 3) ? add : 0u;
                }
            }
            jj += 64; ii += 10; if (jj >= NB) { jj -= NB; ii++; }
        }
    }
    unsigned ex[4];                        // intra-warp exclusive, packed
#pragma unroll
    for (int r = 0; r < 4; r++) {
        unsigned inc = pk[r];
#pragma unroll
        for (int o = 1; o < 32; o <<= 1) {
            unsigned x = __shfl_up_sync(0xffffffffu, inc, o);
            if (lid >= o) inc += x;
        }
        ex[r] = inc - pk[r];
        if (lid == 31) sWT[wid * 4 + r] = inc;
    }
    __syncthreads();
    if (wid == 0) {                        // cross-warp scan (32 warps -> 32 lanes)
#pragma unroll
        for (int r = 0; r < 4; r++) {
            unsigned own = sWT[lid * 4 + r];
            unsigned inc = own;
#pragma unroll
            for (int o = 1; o < 32; o <<= 1) {
                unsigned x = __shfl_up_sync(0xffffffffu, inc, o);
                if (lid >= o) inc += x;
            }
            sWB[lid * 4 + r] = inc - own;
            if (lid == 31) sTot4[r] = inc;
        }
    }
    __syncthreads();

    int start[NCLS];                       // my scatter cursors (static access only)
    int base8;
    {
        int b = 0;
        int off0 = 0;
#pragma unroll
        for (int c = 0; c < NCLS; c++) {
            int tot = (int)((sTot4[c >> 1] >> ((c & 1) * 16)) & 0xFFFFu);
            int wb  = (int)((sWB[wid * 4 + (c >> 1)] >> ((c & 1) * 16)) & 0xFFFFu);
            int eo  = (int)((ex[c >> 1] >> ((c & 1) * 16)) & 0xFFFFu);
            start[c] = b + wb + eo;
            if (t == 0) sOff[c] = b;
            off0 = b + tot;
            b = (b + tot + 3) & ~3;        // 4-elem aligned segments
        }
        (void)off0;
        if (t == 0) sOff[NCLS] = b;
        base8 = b;
    }
    for (int x = t; x < base8; x += BTHR) { sPD[x] = -CUDART_INF_F; sPM[x] = 0; }

    // ================= Phase 1b: finish distances =================
    float myPos = 0.f, myNeg = 0.f;
    if (have) {
        float dx = va.x - vb.x, dy = va.y - vb.y, dz = va.z - vb.z, dw = va.w - vb.w;
        float d2 = dx * dx + dy * dy + dz * dz + dw * dw;
#pragma unroll
        for (int o = 16; o; o >>= 1) d2 += __shfl_down_sync(0xffffffffu, d2, o);
        if (lid == 0) {
            float dm = sqrtf(fmaxf(d2, 0.f) + 1e-16f);
            g_Dm[pi * NB + pj] = dm;
            g_Dm[pj * NB + pi] = dm;
            if (sLab[pi] == sLab[pj]) myPos = dm; else myNeg = dm;
        }
    }
    // residual pairs (only if the grid is unexpectedly small)
    for (int p2 = p + nblk * 32; p2 < NUND; p2 += nblk * 32) {
        float s = sqrtf((float)(36481 - 8 * p2));
        int i = (int)((191.0f - s) * 0.5f);
        while ((i + 1) * (191 - (i + 1)) / 2 <= p2) ++i;
        while (i * (191 - i) / 2 > p2) --i;
        int j = i + 1 + (p2 - i * (191 - i) / 2);
        const float4 a2 = ((const float4*)(E + i * ND))[lid];
        const float4 b2 = ((const float4*)(E + j * ND))[lid];
        float dx = a2.x - b2.x, dy = a2.y - b2.y, dz = a2.z - b2.z, dw = a2.w - b2.w;
        float d2 = dx * dx + dy * dy + dz * dz + dw * dw;
#pragma unroll
        for (int o = 16; o; o >>= 1) d2 += __shfl_down_sync(0xffffffffu, d2, o);
        if (lid == 0) {
            float dm = sqrtf(fmaxf(d2, 0.f) + 1e-16f);
            g_Dm[i * NB + j] = dm;
            g_Dm[j * NB + i] = dm;
            if (sLab[i] == sLab[j]) myPos += dm; else myNeg += dm;
        }
    }
    if (lid == 0) { sF1[wid] = myPos; sF2[wid] = myNeg; }
    __syncthreads();

    // ================= barrier A (grid residency-clamped => spin safe) ===========
    if (t == 0) {
        float pS = 0.f, nS = 0.f;
#pragma unroll
        for (int w = 0; w < 32; w++) { pS += sF1[w]; nS += sF2[w]; }
        g_bP[blockIdx.x] = pS; g_bN[blockIdx.x] = nS;
        __threadfence();
        if (atomicAdd(&g_ctrA, 1) == nblk - 1) g_flagA = 1;
        else while (g_flagA == 0) __nanosleep(64);
        __threadfence();
    }
    __syncthreads();

    // ---- thr (warp 0; deterministic fixed order => identical in every block) ----
    if (wid == 0) {
        float pS = 0.f, nS = 0.f;
        for (int w = lid; w < nblk; w += 32) { pS += g_bP[w]; nS += g_bN[w]; }
#pragma unroll
        for (int o = 16; o; o >>= 1) {
            pS += __shfl_down_sync(0xffffffffu, pS, o);
            nS += __shfl_down_sync(0xffffffffu, nS, o);
        }
        if (lid == 0) {
            int s2 = 0;
#pragma unroll
            for (int c = 0; c < NCLS; c++) { int h = sHist[c]; s2 += h * h; }
            float cpos = (float)(s2 - NB);          // directed same-label pairs
            float cneg = (float)(NPAIR - s2);       // directed diff-label pairs
            float mu = (cpos > 0.f && cneg > 0.f)
                       ? ((2.f * nS) / cneg - (2.f * pS) / cpos) : 0.f;
            sThr = fmaxf(mu, 0.f);
        }
    }

    // ---- scatter pos pairs (same traversal order as counting pass) ----
    {
        int ii = t / NB, jj = t - (t / NB) * NB, idx = t;
#pragma unroll 1
        for (int it = 0; it < NPAIR / BTHR; it++) {
            if (ii < jj) {
                int li = sLab[ii];
                if (li == sLab[jj]) {
                    int s2 = 0;
#pragma unroll
                    for (int c = 0; c < NCLS; c++) { if (li == c) s2 = start[c]++; }
                    sPD[s2] = g_Dm[idx];
                    sPM[s2] = ii | (jj << 8) | (li << 16);
                }
            }
            jj += 64; ii += 10; idx += BTHR; if (jj >= NB) { jj -= NB; ii++; }
        }
    }
    __syncthreads();

    const float thr = sThr, thrh = 0.5f * thr;

    // ================= Phase 2: quad (undirected neg, weighted) + triplet =========
    float qs = 0.f, ts = 0.f; unsigned qc = 0, tc = 0;
    const int gt = blockIdx.x * BTHR + t;
    const int GT = nblk * BTHR;

    // quad item = (pair idx, segment seg, quarter); active iff undirected neg pair
    const int qTot = NPAIR * NCLS * 4;
    for (int e = gt; e < qTot; e += GT) {
        int idx = e >> 5;
        int ii = idx / NB, jj = idx - ii * NB;
        if (ii >= jj) continue;
        int li = sLab[ii], lj = sLab[jj];
        if (li == lj) continue;                    // not a negative pair
        float b = g_Dm[idx];                       // L2, issued early
        int seg = (e >> 2) & 7, quar = e & 3;
        int lo = sOff[seg], hi = sOff[seg + 1];
        int qlen = ((hi - lo + 15) >> 4) << 2;     // 4-aligned quarter length
        int xs = lo + quar * qlen;
        int xe = min(xs + qlen, hi);
        int wi = 2 - (seg == li) - (seg == lj);    // in {1,2}
        float ls = 0.f; int lc = 0;
        for (int x = xs; x < xe; x += 4) {
            const float4 v = *reinterpret_cast<const float4*>(&sPD[x]);
            float d0 = b - v.x, d1 = b - v.y, d2 = b - v.z, d3 = b - v.w;
            if (d0 < thrh) { lc++; ls += fmaxf(d0, 0.f); }
            if (d1 < thrh) { lc++; ls += fmaxf(d1, 0.f); }
            if (d2 < thrh) { lc++; ls += fmaxf(d2, 0.f); }
            if (d3 < thrh) { lc++; ls += fmaxf(d3, 0.f); }
        }
        qs = fmaf((float)wi, ls, qs);
        qc += (unsigned)(wi * lc);
    }

    // triplet: item = (padded pos slot pp, negative k); both anchor orientations
    for (int e = gt; e < base8 * NB; e += GT) {
        int pp = e / NB, k = e - pp * NB;
        int meta = sPM[pp];
        int ai = meta & 255, aj = (meta >> 8) & 255, c = meta >> 16;
        float dij = sPD[pp];                       // -INF pads => +INF diffs => skipped
        if (sLab[k] != c) {
            float tv1 = g_Dm[ai * NB + k] - dij;
            float tv2 = g_Dm[aj * NB + k] - dij;
            if (tv1 < thr) { tc++; ts += fmaxf(tv1, 0.f); }
            if (tv2 < thr) { tc++; ts += fmaxf(tv2, 0.f); }
        }
    }

    // ================= Phase 3: reduce + combine =================
#pragma unroll
    for (int o = 16; o; o >>= 1) {
        qs += __shfl_down_sync(0xffffffffu, qs, o);
        ts += __shfl_down_sync(0xffffffffu, ts, o);
        qc += __shfl_down_sync(0xffffffffu, qc, o);
        tc += __shfl_down_sync(0xffffffffu, tc, o);
    }
    if ((t & 31) == 0) { sF1[wid] = qs; sF2[wid] = ts; sC1[wid] = qc; sC2[wid] = tc; }
    __syncthreads();
    if (t < 32) {
        qs = sF1[t]; ts = sF2[t]; qc = sC1[t]; tc = sC2[t];
#pragma unroll
        for (int o = 16; o; o >>= 1) {
            qs += __shfl_down_sync(0xffffffffu, qs, o);
            ts += __shfl_down_sync(0xffffffffu, ts, o);
            qc += __shfl_down_sync(0xffffffffu, qc, o);
            tc += __shfl_down_sync(0xffffffffu, tc, o);
        }
    }
    __syncthreads();
    if (t == 0) {
        g_pQ[blockIdx.x] = qs; g_pT[blockIdx.x] = ts;
        g_pQC[blockIdx.x] = qc; g_pTC[blockIdx.x] = tc;
        __threadfence();
        sLast = (atomicAdd(&g_ctrB, 1) == nblk - 1);
    }
    __syncthreads();
    if (!sLast) return;

    if (t < 32) {
        float a = 0.f, b = 0.f; unsigned c1 = 0, c2 = 0;
        for (int w = t; w < nblk; w += 32) {
            a += g_pQ[w]; b += g_pT[w]; c1 += g_pQC[w]; c2 += g_pTC[w];
        }
#pragma unroll
        for (int o = 16; o; o >>= 1) {
            a  += __shfl_down_sync(0xffffffffu, a, o);
            b  += __shfl_down_sync(0xffffffffu, b, o);
            c1 += __shfl_down_sync(0xffffffffu, c1, o);
            c2 += __shfl_down_sync(0xffffffffu, c2, o);
        }
        if (t == 0) {
            float tl = (c2 > 0) ? b / (float)c2 : 0.f;
            float ql = (c1 > 0) ? a / (float)c1 : 0.f;
            out[0] = tl + ql;
            g_ctrA = 0; g_ctrB = 0; g_flagA = 0;    // reset for next replay
        }
    }
}

extern "C" void kernel_launch(void* const* d_in, const int* in_sizes, int n_in,
                              void* d_out, int out_size) {
    const float* E = (const float*)d_in[0];
    const void* lab = d_in[1];
    (void)in_sizes; (void)n_in; (void)out_size;
    int sms = 148;
    cudaDeviceGetAttribute(&sms, cudaDevAttrMultiProcessorCount, 0);
    // clamp grid to PROVABLE single-wave residency (spin barrier safety)
    int perSM = 1;
    cudaOccupancyMaxActiveBlocksPerMultiprocessor(&perSM, kFused, BTHR, 0);
    if (perSM < 1) perSM = 1;
    long cap = (long)perSM * sms;
    int grid = sms < MAXBLK ? sms : MAXBLK;
    if (grid > cap) grid = (int)cap;
    if (grid < 1) grid = 1;
    kFused<<<grid, BTHR>>>(E, lab, (float*)d_out);
}